// round 2
// baseline (speedup 1.0000x reference)
#include <cuda_runtime.h>
#include <math.h>

#define BSZ 4096
#define DIM 256
#define NF  12288            // 3 * BSZ rows: [A ; P0 ; P1]
#define MARGIN 1.0f
#define EPSQ 1e-12f

// Scratch (allocation-free rule: __device__ globals)
__device__ float    g_F[NF * DIM];        // normalized rows, 12.6 MB
__device__ float    g_pos[2 * BSZ];       // dot(a_i, p_{i,v})
__device__ unsigned g_maxkey[3 * BSZ];    // order-preserving encoded max dot

// ---- monotone float <-> uint encoding (for atomicMax over signed floats) ----
__device__ __forceinline__ unsigned enc_key(float f) {
    unsigned b = __float_as_uint(f);
    return (b & 0x80000000u) ? ~b : (b | 0x80000000u);
}
__device__ __forceinline__ float dec_key(unsigned k) {
    unsigned b = (k & 0x80000000u) ? (k & 0x7fffffffu) : ~k;
    return __uint_as_float(b);
}

// ---- block-wide sum reduce (256 threads), result broadcast to all ----
__device__ __forceinline__ float block_sum_all(float v, float* sm) {
    #pragma unroll
    for (int o = 16; o; o >>= 1) v += __shfl_down_sync(0xffffffffu, v, o);
    int w = threadIdx.x >> 5, l = threadIdx.x & 31;
    if (l == 0) sm[w] = v;
    __syncthreads();
    if (w == 0) {
        float t = (l < 8) ? sm[l] : 0.0f;
        #pragma unroll
        for (int o = 4; o; o >>= 1) t += __shfl_down_sync(0xffffffffu, t, o);
        if (l == 0) sm[0] = t;
    }
    __syncthreads();
    float r = sm[0];
    __syncthreads();
    return r;
}

// ============================================================================
// Kernel 1: normalize rows into g_F, compute positive-pair dots, init maxkeys
// ============================================================================
__global__ __launch_bounds__(DIM) void normalize_kernel(
    const float* __restrict__ anchor, const float* __restrict__ positive) {
    __shared__ float sm[32];
    int i = blockIdx.x, t = threadIdx.x;

    float a  = anchor[i * DIM + t];
    float ss = block_sum_all(a * a, sm);
    float an = a / fmaxf(sqrtf(ss), 1e-12f);
    g_F[i * DIM + t] = an;

    #pragma unroll
    for (int v = 0; v < 2; v++) {
        float p  = positive[(i * 2 + v) * DIM + t];
        float ps = block_sum_all(p * p, sm);
        float pn = p / fmaxf(sqrtf(ps), 1e-12f);
        g_F[((1 + v) * BSZ + i) * DIM + t] = pn;
        float pd = block_sum_all(an * pn, sm);
        if (t == 0) g_pos[v * BSZ + i] = pd;
    }
    if (t < 3) g_maxkey[t * BSZ + i] = enc_key(-2.0f);
}

// ============================================================================
// Kernel 2: fused GEMM + masked row-max.
// C[i, j] = dot(A_i, F_j) over F = [A; P0; P1] (cols = 12288).
// Per row i: max over cols j with labels[j % 4096] != labels[i], tracked
// separately per source matrix via atomicMax on g_maxkey[mat*BSZ + i].
// Tile: 128x128, BK=8, 256 threads, 8x8 per thread.
// ============================================================================
#define BM 128
#define BN 128
#define BK 8

__global__ __launch_bounds__(256) void gemm_max_kernel(const int* __restrict__ labels) {
    __shared__ float As[BK][BM];
    __shared__ float Bs[BK][BN];
    __shared__ float red[BM][17];      // padded to dodge bank conflicts
    __shared__ int   rlab[BM], clab[BN];

    int colBase = blockIdx.x * BN;     // 0..12287
    int rowBase = blockIdx.y * BM;     // 0..4095
    int tid = threadIdx.x;
    int tx = tid & 15, ty = tid >> 4;

    if (tid < BM) {
        rlab[tid] = labels[rowBase + tid];
        clab[tid] = labels[(colBase & (BSZ - 1)) + tid];   // labels repeat per matrix
    }

    float acc[8][8];
    #pragma unroll
    for (int m = 0; m < 8; m++)
        #pragma unroll
        for (int n = 0; n < 8; n++) acc[m][n] = 0.0f;

    int lr = tid >> 1;                 // 0..127 : row within tile
    int lk = (tid & 1) * 4;            // 0 or 4 : k-quad within BK
    const float* Aptr = g_F + (size_t)(rowBase + lr) * DIM + lk;
    const float* Bptr = g_F + (size_t)(colBase + lr) * DIM + lk;

    for (int kt = 0; kt < DIM; kt += BK) {
        float4 av = *(const float4*)(Aptr + kt);
        float4 bv = *(const float4*)(Bptr + kt);
        __syncthreads();
        As[lk + 0][lr] = av.x; As[lk + 1][lr] = av.y;
        As[lk + 2][lr] = av.z; As[lk + 3][lr] = av.w;
        Bs[lk + 0][lr] = bv.x; Bs[lk + 1][lr] = bv.y;
        Bs[lk + 2][lr] = bv.z; Bs[lk + 3][lr] = bv.w;
        __syncthreads();

        #pragma unroll
        for (int k = 0; k < BK; k++) {
            float4 ra0 = *(const float4*)&As[k][ty * 8];
            float4 ra1 = *(const float4*)&As[k][ty * 8 + 4];
            float4 rb0 = *(const float4*)&Bs[k][tx * 8];
            float4 rb1 = *(const float4*)&Bs[k][tx * 8 + 4];
            float ra[8] = {ra0.x, ra0.y, ra0.z, ra0.w, ra1.x, ra1.y, ra1.z, ra1.w};
            float rb[8] = {rb0.x, rb0.y, rb0.z, rb0.w, rb1.x, rb1.y, rb1.z, rb1.w};
            #pragma unroll
            for (int m = 0; m < 8; m++)
                #pragma unroll
                for (int n = 0; n < 8; n++)
                    acc[m][n] = fmaf(ra[m], rb[n], acc[m][n]);
        }
    }

    // Epilogue: masked max per row
    __syncthreads();
    #pragma unroll
    for (int m = 0; m < 8; m++) {
        int   rl = rlab[ty * 8 + m];
        float mx = -2.0f;
        #pragma unroll
        for (int n = 0; n < 8; n++) {
            if (clab[tx * 8 + n] != rl) mx = fmaxf(mx, acc[m][n]);
        }
        red[ty * 8 + m][tx] = mx;
    }
    __syncthreads();
    if (tid < BM) {
        float mx = -2.0f;
        #pragma unroll
        for (int j = 0; j < 16; j++) mx = fmaxf(mx, red[tid][j]);
        int mat = colBase >> 12;       // 0: aa, 1: ap0, 2: ap1
        atomicMax(&g_maxkey[mat * BSZ + rowBase + tid], enc_key(mx));
    }
}

// ============================================================================
// Kernel 3: deterministic finalize -> scalar mean loss
// ============================================================================
__global__ __launch_bounds__(1024) void finalize_kernel(float* __restrict__ out) {
    __shared__ float sm[32];
    float sum = 0.0f;
    for (int i = threadIdx.x; i < BSZ; i += 1024) {
        float daa = dec_key(g_maxkey[i]);
        #pragma unroll
        for (int v = 0; v < 2; v++) {
            float dap  = dec_key(g_maxkey[(1 + v) * BSZ + i]);
            float best = fmaxf(daa, dap);
            float neg  = sqrtf(fmaxf(2.0f - 2.0f * best, EPSQ));
            float pos  = sqrtf(fmaxf(2.0f - 2.0f * g_pos[v * BSZ + i], EPSQ));
            sum += fmaxf(pos - neg + MARGIN, 0.0f);
        }
    }
    // deterministic block reduction
    #pragma unroll
    for (int o = 16; o; o >>= 1) sum += __shfl_down_sync(0xffffffffu, sum, o);
    int w = threadIdx.x >> 5, l = threadIdx.x & 31;
    if (l == 0) sm[w] = sum;
    __syncthreads();
    if (w == 0) {
        float t = sm[l];
        #pragma unroll
        for (int o = 16; o; o >>= 1) t += __shfl_down_sync(0xffffffffu, t, o);
        if (l == 0) out[0] = t / (2.0f * BSZ);
    }
}

// ============================================================================
extern "C" void kernel_launch(void* const* d_in, const int* in_sizes, int n_in,
                              void* d_out, int out_size) {
    const float* anchor   = (const float*)d_in[0];
    const float* positive = (const float*)d_in[1];
    const int*   labels   = (const int*)d_in[2];
    float*       out      = (float*)d_out;

    normalize_kernel<<<BSZ, DIM>>>(anchor, positive);
    gemm_max_kernel<<<dim3(NF / BN, BSZ / BM), 256>>>(labels);
    finalize_kernel<<<1, 1024>>>(out);
}

// round 9
// speedup vs baseline: 4.7713x; 4.7713x over previous
#include <cuda_runtime.h>
#include <cuda_bf16.h>
#include <cstdint>
#include <math.h>

#define BSZ 4096
#define DIM 256
#define NF  12288            // 3 * BSZ rows: [A ; P0 ; P1]
#define MARGIN 1.0f
#define EPSQ 1e-12f
#define ASTRIDE 40           // smem row stride in bf16 (80 B -> conflict-free ldmatrix)

// ---------------- scratch (__device__ globals; no allocs allowed) -----------
__device__ __nv_bfloat16 g_Fh[NF * DIM];   // normalized rows, bf16 (GEMM)
__device__ float         g_pos[2 * BSZ];   // exact fp32 dot(a_i, p_{i,v})
__device__ unsigned      g_maxkey[3 * BSZ];

__device__ __forceinline__ uint32_t smem_to_u32(const void* p) {
    uint32_t a;
    asm("{ .reg .u64 t; cvta.to.shared.u64 t, %1; cvt.u32.u64 %0, t; }" : "=r"(a) : "l"(p));
    return a;
}

// ---- monotone float <-> uint encoding (atomicMax over signed floats) -------
__device__ __forceinline__ unsigned enc_key(float f) {
    unsigned b = __float_as_uint(f);
    return (b & 0x80000000u) ? ~b : (b | 0x80000000u);
}
__device__ __forceinline__ float dec_key(unsigned k) {
    unsigned b = (k & 0x80000000u) ? (k & 0x7fffffffu) : ~k;
    return __uint_as_float(b);
}

// ---- block-wide sum reduce (256 threads), result broadcast -----------------
__device__ __forceinline__ float block_sum_all(float v, float* sm) {
    #pragma unroll
    for (int o = 16; o; o >>= 1) v += __shfl_down_sync(0xffffffffu, v, o);
    int w = threadIdx.x >> 5, l = threadIdx.x & 31;
    if (l == 0) sm[w] = v;
    __syncthreads();
    if (w == 0) {
        float t = (l < 8) ? sm[l] : 0.0f;
        #pragma unroll
        for (int o = 4; o; o >>= 1) t += __shfl_down_sync(0xffffffffu, t, o);
        if (l == 0) sm[0] = t;
    }
    __syncthreads();
    float r = sm[0];
    __syncthreads();
    return r;
}

// ============================================================================
// Kernel 1: normalize -> bf16 features; exact fp32 positive dots
// ============================================================================
__global__ __launch_bounds__(DIM) void normalize_kernel(
    const float* __restrict__ anchor, const float* __restrict__ positive) {
    __shared__ float sm[32];
    int i = blockIdx.x, t = threadIdx.x;

    float a  = anchor[i * DIM + t];
    float ss = block_sum_all(a * a, sm);
    float an = a / fmaxf(sqrtf(ss), 1e-12f);
    g_Fh[i * DIM + t] = __float2bfloat16(an);

    #pragma unroll
    for (int v = 0; v < 2; v++) {
        float p  = positive[(i * 2 + v) * DIM + t];
        float ps = block_sum_all(p * p, sm);
        float pn = p / fmaxf(sqrtf(ps), 1e-12f);
        g_Fh[((size_t)(1 + v) * BSZ + i) * DIM + t] = __float2bfloat16(pn);
        float pd = block_sum_all(an * pn, sm);
        if (t == 0) g_pos[v * BSZ + i] = pd;
    }
    if (t < 3) g_maxkey[t * BSZ + i] = enc_key(-2.0f);
}

// ============================================================================
// Kernel 2: bf16 tensor-core GEMM (mma.sync.m16n8k16) + fused masked row-max.
// CTA tile 128x128, BK=32, 8 warps; warp tile 32x64 = 2x8 mma fragments.
// B smem layout is [n][k]  ->  ldmatrix WITHOUT .trans gives the correct
// col-major B fragment (n = t/4, k-pairs).  (.trans here was the R4-R8 bug.)
// ============================================================================
__global__ __launch_bounds__(256) void gemm_max_mma(const int* __restrict__ labels) {
    __shared__ __nv_bfloat16 sA[128 * ASTRIDE];
    __shared__ __nv_bfloat16 sB[128 * ASTRIDE];
    __shared__ int clab[128];

    int tid = threadIdx.x, lane = tid & 31, wid = tid >> 5;
    int rowBase = blockIdx.y * 128;    // [0, 4096)
    int colBase = blockIdx.x * 128;    // [0, 12288)
    if (tid < 128) clab[tid] = labels[(colBase & (BSZ - 1)) + tid];

    int warpM = wid & 3;               // 4 warps along M (32 rows each)
    int warpN = wid >> 2;              // 2 warps along N (64 cols each)

    uint32_t sAu = smem_to_u32(sA), sBu = smem_to_u32(sB);

    // ldmatrix lane addressing (bytes), k-step 0; += 32 B per k-step of 16
    uint32_t addrA[2], addrB[4];
    #pragma unroll
    for (int mt = 0; mt < 2; mt++) {
        int r  = warpM * 32 + mt * 16 + (lane & 15);
        int kc = (lane >> 4) * 8;
        addrA[mt] = sAu + (uint32_t)(r * ASTRIDE + kc) * 2u;
    }
    #pragma unroll
    for (int np = 0; np < 4; np++) {
        int n  = warpN * 64 + np * 16 + (lane & 7) + ((lane & 16) >> 1);
        int kc = ((lane >> 3) & 1) * 8;
        addrB[np] = sBu + (uint32_t)(n * ASTRIDE + kc) * 2u;
    }

    float acc[2][8][4];
    #pragma unroll
    for (int mt = 0; mt < 2; mt++)
        #pragma unroll
        for (int nt = 0; nt < 8; nt++)
            #pragma unroll
            for (int c = 0; c < 4; c++) acc[mt][nt][c] = 0.0f;

    int ldrow = tid >> 2, ldg = (tid & 3) * 8;     // 64 rows/pass, 4x8 bf16 per row
    const __nv_bfloat16* gA = g_Fh + (size_t)(rowBase + ldrow) * DIM + ldg;
    const __nv_bfloat16* gB = g_Fh + (size_t)(colBase + ldrow) * DIM + ldg;

    for (int kt = 0; kt < DIM; kt += 32) {
        __syncthreads();
        #pragma unroll
        for (int p = 0; p < 2; p++) {
            *(uint4*)&sA[(ldrow + p * 64) * ASTRIDE + ldg] =
                *(const uint4*)(gA + (size_t)p * 64 * DIM + kt);
            *(uint4*)&sB[(ldrow + p * 64) * ASTRIDE + ldg] =
                *(const uint4*)(gB + (size_t)p * 64 * DIM + kt);
        }
        __syncthreads();

        #pragma unroll
        for (int ks = 0; ks < 2; ks++) {
            uint32_t a[2][4], b[4][4];
            #pragma unroll
            for (int mt = 0; mt < 2; mt++)
                asm volatile("ldmatrix.sync.aligned.m8n8.x4.shared.b16 "
                             "{%0,%1,%2,%3}, [%4];"
                             : "=r"(a[mt][0]), "=r"(a[mt][1]),
                               "=r"(a[mt][2]), "=r"(a[mt][3])
                             : "r"(addrA[mt] + ks * 32u));
            #pragma unroll
            for (int np = 0; np < 4; np++)
                asm volatile("ldmatrix.sync.aligned.m8n8.x4.shared.b16 "
                             "{%0,%1,%2,%3}, [%4];"
                             : "=r"(b[np][0]), "=r"(b[np][1]),
                               "=r"(b[np][2]), "=r"(b[np][3])
                             : "r"(addrB[np] + ks * 32u));
            #pragma unroll
            for (int mt = 0; mt < 2; mt++)
                #pragma unroll
                for (int nt = 0; nt < 8; nt++) {
                    uint32_t b0 = b[nt >> 1][(nt & 1) * 2];
                    uint32_t b1 = b[nt >> 1][(nt & 1) * 2 + 1];
                    asm volatile(
                        "mma.sync.aligned.m16n8k16.row.col.f32.bf16.bf16.f32 "
                        "{%0,%1,%2,%3}, {%4,%5,%6,%7}, {%8,%9}, {%0,%1,%2,%3};"
                        : "+f"(acc[mt][nt][0]), "+f"(acc[mt][nt][1]),
                          "+f"(acc[mt][nt][2]), "+f"(acc[mt][nt][3])
                        : "r"(a[mt][0]), "r"(a[mt][1]), "r"(a[mt][2]), "r"(a[mt][3]),
                          "r"(b0), "r"(b1));
                }
        }
    }

    // Epilogue: masked max per row, straight from C fragments.
    // c0,c1 -> row gid; c2,c3 -> row gid+8; cols nt*8 + qid*2 + {0,1}
    int gid = lane >> 2, qid = lane & 3;
    int mat = colBase >> 12;
    #pragma unroll
    for (int mt = 0; mt < 2; mt++)
        #pragma unroll
        for (int half = 0; half < 2; half++) {
            int grow = rowBase + warpM * 32 + mt * 16 + half * 8 + gid;
            int rl   = labels[grow];
            float mx = -2.0f;
            #pragma unroll
            for (int nt = 0; nt < 8; nt++) {
                int c0 = warpN * 64 + nt * 8 + qid * 2;
                if (clab[c0]     != rl) mx = fmaxf(mx, acc[mt][nt][half * 2]);
                if (clab[c0 + 1] != rl) mx = fmaxf(mx, acc[mt][nt][half * 2 + 1]);
            }
            mx = fmaxf(mx, __shfl_xor_sync(0xffffffffu, mx, 1));
            mx = fmaxf(mx, __shfl_xor_sync(0xffffffffu, mx, 2));
            if (qid == 0)
                atomicMax(&g_maxkey[mat * BSZ + grow], enc_key(mx));
        }
}

// ============================================================================
// Kernel 3: deterministic finalize -> scalar mean loss
// ============================================================================
__global__ __launch_bounds__(1024) void finalize_kernel(float* __restrict__ out) {
    __shared__ float sm[32];
    float sum = 0.0f;
    for (int i = threadIdx.x; i < BSZ; i += 1024) {
        float daa = dec_key(g_maxkey[i]);
        #pragma unroll
        for (int v = 0; v < 2; v++) {
            float dap  = dec_key(g_maxkey[(1 + v) * BSZ + i]);
            float best = fmaxf(daa, dap);
            float neg  = sqrtf(fmaxf(2.0f - 2.0f * best, EPSQ));
            float pos  = sqrtf(fmaxf(2.0f - 2.0f * g_pos[v * BSZ + i], EPSQ));
            sum += fmaxf(pos - neg + MARGIN, 0.0f);
        }
    }
    #pragma unroll
    for (int o = 16; o; o >>= 1) sum += __shfl_down_sync(0xffffffffu, sum, o);
    int w = threadIdx.x >> 5, l = threadIdx.x & 31;
    if (l == 0) sm[w] = sum;
    __syncthreads();
    if (w == 0) {
        float t = sm[l];
        #pragma unroll
        for (int o = 16; o; o >>= 1) t += __shfl_down_sync(0xffffffffu, t, o);
        if (l == 0) out[0] = t / (2.0f * BSZ);
    }
}

// ============================================================================
extern "C" void kernel_launch(void* const* d_in, const int* in_sizes, int n_in,
                              void* d_out, int out_size) {
    const float* anchor   = (const float*)d_in[0];
    const float* positive = (const float*)d_in[1];
    const int*   labels   = (const int*)d_in[2];
    float*       out      = (float*)d_out;

    normalize_kernel<<<BSZ, DIM>>>(anchor, positive);
    gemm_max_mma<<<dim3(NF / 128, BSZ / 128), 256>>>(labels);
    finalize_kernel<<<1, 1024>>>(out);
}

// round 12
// speedup vs baseline: 6.5639x; 1.3757x over previous
#include <cuda_runtime.h>
#include <cuda_bf16.h>
#include <cstdint>
#include <string.h>
#include <math.h>

#define BSZ 4096
#define DIM 256
#define NF  12288            // 3 * BSZ rows: [A ; P0 ; P1]
#define MARGIN 1.0f
#define EPSQ 1e-12f
#define ASTRIDE 40           // smem row stride in bf16 (80 B -> conflict-free ldmatrix)
#define BUFBYTES (128 * ASTRIDE * 2)   // one stage of one operand, bytes

// ---------------- scratch (__device__ globals; no allocs allowed) -----------
__device__ __nv_bfloat16 g_Fh[NF * DIM];   // normalized rows, bf16 (GEMM)
__device__ float         g_pos[2 * BSZ];   // exact fp32 dot(a_i, p_{i,v})
__device__ unsigned      g_maxkey[3 * BSZ];

__device__ __forceinline__ uint32_t smem_to_u32(const void* p) {
    uint32_t a;
    asm("{ .reg .u64 t; cvta.to.shared.u64 t, %1; cvt.u32.u64 %0, t; }" : "=r"(a) : "l"(p));
    return a;
}
__device__ __forceinline__ void cp_async16(uint32_t saddr, const void* gaddr) {
    asm volatile("cp.async.ca.shared.global [%0], [%1], 16;"
                 :: "r"(saddr), "l"(gaddr) : "memory");
}
#define CP_COMMIT()  asm volatile("cp.async.commit_group;" ::: "memory")
#define CP_WAIT(n)   asm volatile("cp.async.wait_group %0;" :: "n"(n) : "memory")

// pack two floats -> bf16x2 bits
__device__ __forceinline__ uint32_t pack_bf16x2(float lo, float hi) {
    __nv_bfloat162 h = __floats2bfloat162_rn(lo, hi);
    uint32_t u;
    memcpy(&u, &h, 4);
    return u;
}

// ---- monotone float <-> uint encoding (atomicMax over signed floats) -------
__device__ __forceinline__ unsigned enc_key(float f) {
    unsigned b = __float_as_uint(f);
    return (b & 0x80000000u) ? ~b : (b | 0x80000000u);
}
__device__ __forceinline__ float dec_key(unsigned k) {
    unsigned b = (k & 0x80000000u) ? (k & 0x7fffffffu) : ~k;
    return __uint_as_float(b);
}

// ============================================================================
// Kernel 1: warp-per-row normalize (no block barriers).
// Lane holds 8 floats of the 256-dim row; shfl-xor reductions only.
// ============================================================================
__global__ __launch_bounds__(256) void normalize_kernel(
    const float* __restrict__ anchor, const float* __restrict__ positive) {
    int gw   = (blockIdx.x * 256 + threadIdx.x) >> 5;   // row 0..4095
    int lane = threadIdx.x & 31;

    // ---- anchor ----
    const float4* a4 = (const float4*)(anchor + (size_t)gw * DIM);
    float4 a0 = a4[lane * 2], a1 = a4[lane * 2 + 1];
    float ss = a0.x*a0.x + a0.y*a0.y + a0.z*a0.z + a0.w*a0.w
             + a1.x*a1.x + a1.y*a1.y + a1.z*a1.z + a1.w*a1.w;
    #pragma unroll
    for (int o = 16; o; o >>= 1) ss += __shfl_xor_sync(0xffffffffu, ss, o);
    float inv = 1.0f / fmaxf(sqrtf(ss), 1e-12f);
    a0.x *= inv; a0.y *= inv; a0.z *= inv; a0.w *= inv;
    a1.x *= inv; a1.y *= inv; a1.z *= inv; a1.w *= inv;
    {
        uint4 o;
        o.x = pack_bf16x2(a0.x, a0.y);
        o.y = pack_bf16x2(a0.z, a0.w);
        o.z = pack_bf16x2(a1.x, a1.y);
        o.w = pack_bf16x2(a1.z, a1.w);
        ((uint4*)(g_Fh + (size_t)gw * DIM))[lane] = o;
    }

    // ---- positives ----
    #pragma unroll
    for (int v = 0; v < 2; v++) {
        const float4* p4 = (const float4*)(positive + ((size_t)gw * 2 + v) * DIM);
        float4 p0 = p4[lane * 2], p1 = p4[lane * 2 + 1];
        float ps = p0.x*p0.x + p0.y*p0.y + p0.z*p0.z + p0.w*p0.w
                 + p1.x*p1.x + p1.y*p1.y + p1.z*p1.z + p1.w*p1.w;
        #pragma unroll
        for (int o = 16; o; o >>= 1) ps += __shfl_xor_sync(0xffffffffu, ps, o);
        float pinv = 1.0f / fmaxf(sqrtf(ps), 1e-12f);
        p0.x *= pinv; p0.y *= pinv; p0.z *= pinv; p0.w *= pinv;
        p1.x *= pinv; p1.y *= pinv; p1.z *= pinv; p1.w *= pinv;
        uint4 o;
        o.x = pack_bf16x2(p0.x, p0.y);
        o.y = pack_bf16x2(p0.z, p0.w);
        o.z = pack_bf16x2(p1.x, p1.y);
        o.w = pack_bf16x2(p1.z, p1.w);
        ((uint4*)(g_Fh + ((size_t)(1 + v) * BSZ + gw) * DIM))[lane] = o;

        float pd = a0.x*p0.x + a0.y*p0.y + a0.z*p0.z + a0.w*p0.w
                 + a1.x*p1.x + a1.y*p1.y + a1.z*p1.z + a1.w*p1.w;
        #pragma unroll
        for (int o2 = 16; o2; o2 >>= 1) pd += __shfl_xor_sync(0xffffffffu, pd, o2);
        if (lane == 0) g_pos[v * BSZ + gw] = pd;
    }
    if (lane < 3) g_maxkey[lane * BSZ + gw] = enc_key(-2.0f);
}

// ============================================================================
// Kernel 2: bf16 mma GEMM, 2-stage cp.async pipeline + fused masked row-max.
// CTA tile 128x128, BK=32, 8 warps; warp tile 32x64 = 2x8 mma fragments.
// B smem layout [n][k] -> ldmatrix WITHOUT .trans = col-major B fragment.
// ============================================================================
__global__ __launch_bounds__(256) void gemm_max_mma(const int* __restrict__ labels) {
    __shared__ __nv_bfloat16 sA[2][128 * ASTRIDE];
    __shared__ __nv_bfloat16 sB[2][128 * ASTRIDE];
    __shared__ int clab[128];

    int tid = threadIdx.x, lane = tid & 31, wid = tid >> 5;
    int rowBase = blockIdx.y * 128;    // [0, 4096)
    int colBase = blockIdx.x * 128;    // [0, 12288)
    if (tid < 128) clab[tid] = labels[(colBase & (BSZ - 1)) + tid];

    int warpM = wid & 3;               // 4 warps along M (32 rows each)
    int warpN = wid >> 2;              // 2 warps along N (64 cols each)

    uint32_t sAu = smem_to_u32(sA), sBu = smem_to_u32(sB);

    // ldmatrix lane offsets (bytes, within one stage); += 32 B per k-step
    uint32_t offA[2], offB[4];
    #pragma unroll
    for (int mt = 0; mt < 2; mt++) {
        int r  = warpM * 32 + mt * 16 + (lane & 15);
        int kc = (lane >> 4) * 8;
        offA[mt] = (uint32_t)(r * ASTRIDE + kc) * 2u;
    }
    #pragma unroll
    for (int np = 0; np < 4; np++) {
        int n  = warpN * 64 + np * 16 + (lane & 7) + ((lane & 16) >> 1);
        int kc = ((lane >> 3) & 1) * 8;
        offB[np] = (uint32_t)(n * ASTRIDE + kc) * 2u;
    }

    float acc[2][8][4];
    #pragma unroll
    for (int mt = 0; mt < 2; mt++)
        #pragma unroll
        for (int nt = 0; nt < 8; nt++)
            #pragma unroll
            for (int c = 0; c < 4; c++) acc[mt][nt][c] = 0.0f;

    int ldrow = tid >> 2, ldg = (tid & 3) * 8;     // 64 rows/pass, 16 B per row
    const __nv_bfloat16* gA = g_Fh + (size_t)(rowBase + ldrow) * DIM + ldg;
    const __nv_bfloat16* gB = g_Fh + (size_t)(colBase + ldrow) * DIM + ldg;
    uint32_t sArow = (uint32_t)(ldrow * ASTRIDE + ldg) * 2u;

    // ---- pipeline: issue stage for k-tile kt into buffer buf ----
    auto issue = [&](int buf, int kt) {
        #pragma unroll
        for (int p = 0; p < 2; p++) {
            uint32_t so = (uint32_t)buf * BUFBYTES
                        + (uint32_t)(p * 64 * ASTRIDE * 2);
            cp_async16(sAu + so + sArow, gA + (size_t)p * 64 * DIM + kt);
            cp_async16(sBu + so + sArow, gB + (size_t)p * 64 * DIM + kt);
        }
    };

    issue(0, 0);
    CP_COMMIT();

    #pragma unroll
    for (int i = 0; i < 8; i++) {
        if (i < 7) {
            issue((i + 1) & 1, (i + 1) * 32);
            CP_COMMIT();
            CP_WAIT(1);
        } else {
            CP_WAIT(0);
        }
        __syncthreads();

        uint32_t bufo = (uint32_t)(i & 1) * BUFBYTES;
        #pragma unroll
        for (int ks = 0; ks < 2; ks++) {
            uint32_t a[2][4], b[4][4];
            #pragma unroll
            for (int mt = 0; mt < 2; mt++)
                asm volatile("ldmatrix.sync.aligned.m8n8.x4.shared.b16 "
                             "{%0,%1,%2,%3}, [%4];"
                             : "=r"(a[mt][0]), "=r"(a[mt][1]),
                               "=r"(a[mt][2]), "=r"(a[mt][3])
                             : "r"(sAu + bufo + offA[mt] + ks * 32u));
            #pragma unroll
            for (int np = 0; np < 4; np++)
                asm volatile("ldmatrix.sync.aligned.m8n8.x4.shared.b16 "
                             "{%0,%1,%2,%3}, [%4];"
                             : "=r"(b[np][0]), "=r"(b[np][1]),
                               "=r"(b[np][2]), "=r"(b[np][3])
                             : "r"(sBu + bufo + offB[np] + ks * 32u));
            #pragma unroll
            for (int mt = 0; mt < 2; mt++)
                #pragma unroll
                for (int nt = 0; nt < 8; nt++) {
                    uint32_t b0 = b[nt >> 1][(nt & 1) * 2];
                    uint32_t b1 = b[nt >> 1][(nt & 1) * 2 + 1];
                    asm volatile(
                        "mma.sync.aligned.m16n8k16.row.col.f32.bf16.bf16.f32 "
                        "{%0,%1,%2,%3}, {%4,%5,%6,%7}, {%8,%9}, {%0,%1,%2,%3};"
                        : "+f"(acc[mt][nt][0]), "+f"(acc[mt][nt][1]),
                          "+f"(acc[mt][nt][2]), "+f"(acc[mt][nt][3])
                        : "r"(a[mt][0]), "r"(a[mt][1]), "r"(a[mt][2]), "r"(a[mt][3]),
                          "r"(b0), "r"(b1));
                }
        }
        __syncthreads();
    }

    // Epilogue: masked max per row, straight from C fragments.
    int gid = lane >> 2, qid = lane & 3;
    int mat = colBase >> 12;
    #pragma unroll
    for (int mt = 0; mt < 2; mt++)
        #pragma unroll
        for (int half = 0; half < 2; half++) {
            int grow = rowBase + warpM * 32 + mt * 16 + half * 8 + gid;
            int rl   = labels[grow];
            float mx = -2.0f;
            #pragma unroll
            for (int nt = 0; nt < 8; nt++) {
                int c0 = warpN * 64 + nt * 8 + qid * 2;
                if (clab[c0]     != rl) mx = fmaxf(mx, acc[mt][nt][half * 2]);
                if (clab[c0 + 1] != rl) mx = fmaxf(mx, acc[mt][nt][half * 2 + 1]);
            }
            mx = fmaxf(mx, __shfl_xor_sync(0xffffffffu, mx, 1));
            mx = fmaxf(mx, __shfl_xor_sync(0xffffffffu, mx, 2));
            if (qid == 0)
                atomicMax(&g_maxkey[mat * BSZ + grow], enc_key(mx));
        }
}

// ============================================================================
// Kernel 3: deterministic finalize -> scalar mean loss
// ============================================================================
__global__ __launch_bounds__(1024) void finalize_kernel(float* __restrict__ out) {
    __shared__ float sm[32];
    float sum = 0.0f;
    for (int i = threadIdx.x; i < BSZ; i += 1024) {
        float daa = dec_key(g_maxkey[i]);
        #pragma unroll
        for (int v = 0; v < 2; v++) {
            float dap  = dec_key(g_maxkey[(1 + v) * BSZ + i]);
            float best = fmaxf(daa, dap);
            float neg  = sqrtf(fmaxf(2.0f - 2.0f * best, EPSQ));
            float pos  = sqrtf(fmaxf(2.0f - 2.0f * g_pos[v * BSZ + i], EPSQ));
            sum += fmaxf(pos - neg + MARGIN, 0.0f);
        }
    }
    #pragma unroll
    for (int o = 16; o; o >>= 1) sum += __shfl_down_sync(0xffffffffu, sum, o);
    int w = threadIdx.x >> 5, l = threadIdx.x & 31;
    if (l == 0) sm[w] = sum;
    __syncthreads();
    if (w == 0) {
        float t = sm[l];
        #pragma unroll
        for (int o = 16; o; o >>= 1) t += __shfl_down_sync(0xffffffffu, t, o);
        if (l == 0) out[0] = t / (2.0f * BSZ);
    }
}

// ============================================================================
extern "C" void kernel_launch(void* const* d_in, const int* in_sizes, int n_in,
                              void* d_out, int out_size) {
    const float* anchor   = (const float*)d_in[0];
    const float* positive = (const float*)d_in[1];
    const int*   labels   = (const int*)d_in[2];
    float*       out      = (float*)d_out;

    normalize_kernel<<<BSZ / 8, 256>>>(anchor, positive);
    gemm_max_mma<<<dim3(NF / 128, BSZ / 128), 256>>>(labels);
    finalize_kernel<<<1, 1024>>>(out);
}

// round 13
// speedup vs baseline: 6.8699x; 1.0466x over previous
#include <cuda_runtime.h>
#include <cuda_bf16.h>
#include <cstdint>
#include <string.h>
#include <math.h>

#define BSZ 4096
#define DIM 256
#define NF  12288            // 3 * BSZ rows: [A ; P0 ; P1]
#define MARGIN 1.0f
#define EPSQ 1e-12f
#define ASTRIDE 40           // smem row stride in bf16 (80 B -> conflict-free ldmatrix)
#define OPBYTES   (128 * ASTRIDE * 2)     // one operand, one stage: 10240 B
#define STAGEBYTES (2 * OPBYTES)          // A + B per stage: 20480 B
#define NSTAGE 3
#define SMEM_DYN (NSTAGE * STAGEBYTES + 512)   // + clab

// ---------------- scratch (__device__ globals; no allocs allowed) -----------
__device__ __nv_bfloat16 g_Fh[NF * DIM];   // normalized rows, bf16 (GEMM)
__device__ float         g_pos[2 * BSZ];   // exact fp32 dot(a_i, p_{i,v})
__device__ unsigned      g_maxkey[3 * BSZ];

__device__ __forceinline__ uint32_t smem_to_u32(const void* p) {
    uint32_t a;
    asm("{ .reg .u64 t; cvta.to.shared.u64 t, %1; cvt.u32.u64 %0, t; }" : "=r"(a) : "l"(p));
    return a;
}
__device__ __forceinline__ void cp_async16(uint32_t saddr, const void* gaddr) {
    asm volatile("cp.async.ca.shared.global [%0], [%1], 16;"
                 :: "r"(saddr), "l"(gaddr) : "memory");
}
#define CP_COMMIT()  asm volatile("cp.async.commit_group;" ::: "memory")
#define CP_WAIT(n)   asm volatile("cp.async.wait_group %0;" :: "n"(n) : "memory")

// pack two floats -> bf16x2 bits
__device__ __forceinline__ uint32_t pack_bf16x2(float lo, float hi) {
    __nv_bfloat162 h = __floats2bfloat162_rn(lo, hi);
    uint32_t u;
    memcpy(&u, &h, 4);
    return u;
}

// ---- monotone float <-> uint encoding (atomicMax over signed floats) -------
__device__ __forceinline__ unsigned enc_key(float f) {
    unsigned b = __float_as_uint(f);
    return (b & 0x80000000u) ? ~b : (b | 0x80000000u);
}
__device__ __forceinline__ float dec_key(unsigned k) {
    unsigned b = (k & 0x80000000u) ? (k & 0x7fffffffu) : ~k;
    return __uint_as_float(b);
}

// ============================================================================
// Kernel 1: warp-per-row normalize (no block barriers).
// ============================================================================
__global__ __launch_bounds__(256) void normalize_kernel(
    const float* __restrict__ anchor, const float* __restrict__ positive) {
    int gw   = (blockIdx.x * 256 + threadIdx.x) >> 5;   // row 0..4095
    int lane = threadIdx.x & 31;

    const float4* a4 = (const float4*)(anchor + (size_t)gw * DIM);
    float4 a0 = a4[lane * 2], a1 = a4[lane * 2 + 1];
    float ss = a0.x*a0.x + a0.y*a0.y + a0.z*a0.z + a0.w*a0.w
             + a1.x*a1.x + a1.y*a1.y + a1.z*a1.z + a1.w*a1.w;
    #pragma unroll
    for (int o = 16; o; o >>= 1) ss += __shfl_xor_sync(0xffffffffu, ss, o);
    float inv = 1.0f / fmaxf(sqrtf(ss), 1e-12f);
    a0.x *= inv; a0.y *= inv; a0.z *= inv; a0.w *= inv;
    a1.x *= inv; a1.y *= inv; a1.z *= inv; a1.w *= inv;
    {
        uint4 o;
        o.x = pack_bf16x2(a0.x, a0.y);
        o.y = pack_bf16x2(a0.z, a0.w);
        o.z = pack_bf16x2(a1.x, a1.y);
        o.w = pack_bf16x2(a1.z, a1.w);
        ((uint4*)(g_Fh + (size_t)gw * DIM))[lane] = o;
    }

    #pragma unroll
    for (int v = 0; v < 2; v++) {
        const float4* p4 = (const float4*)(positive + ((size_t)gw * 2 + v) * DIM);
        float4 p0 = p4[lane * 2], p1 = p4[lane * 2 + 1];
        float ps = p0.x*p0.x + p0.y*p0.y + p0.z*p0.z + p0.w*p0.w
                 + p1.x*p1.x + p1.y*p1.y + p1.z*p1.z + p1.w*p1.w;
        #pragma unroll
        for (int o = 16; o; o >>= 1) ps += __shfl_xor_sync(0xffffffffu, ps, o);
        float pinv = 1.0f / fmaxf(sqrtf(ps), 1e-12f);
        p0.x *= pinv; p0.y *= pinv; p0.z *= pinv; p0.w *= pinv;
        p1.x *= pinv; p1.y *= pinv; p1.z *= pinv; p1.w *= pinv;
        uint4 o;
        o.x = pack_bf16x2(p0.x, p0.y);
        o.y = pack_bf16x2(p0.z, p0.w);
        o.z = pack_bf16x2(p1.x, p1.y);
        o.w = pack_bf16x2(p1.z, p1.w);
        ((uint4*)(g_Fh + ((size_t)(1 + v) * BSZ + gw) * DIM))[lane] = o;

        float pd = a0.x*p0.x + a0.y*p0.y + a0.z*p0.z + a0.w*p0.w
                 + a1.x*p1.x + a1.y*p1.y + a1.z*p1.z + a1.w*p1.w;
        #pragma unroll
        for (int o2 = 16; o2; o2 >>= 1) pd += __shfl_xor_sync(0xffffffffu, pd, o2);
        if (lane == 0) g_pos[v * BSZ + gw] = pd;
    }
    if (lane < 3) g_maxkey[lane * BSZ + gw] = enc_key(-2.0f);
}

// ============================================================================
// Kernel 2: bf16 mma GEMM, 3-stage cp.async pipeline, ONE barrier per k-iter.
// CTA tile 128x128, BK=32, 8 warps; warp tile 32x64 = 2x8 mma fragments.
// Stage layout (dynamic smem): [sA | sB] per stage; clab at the end.
// Prefetch at iter i targets stage (i+2)%3, retired at iter i-1 and protected
// by the single top-of-loop __syncthreads.
// ============================================================================
__global__ __launch_bounds__(256) void gemm_max_mma(const int* __restrict__ labels) {
    extern __shared__ char dsm[];
    uint32_t sbase = smem_to_u32(dsm);
    int* clab = (int*)(dsm + NSTAGE * STAGEBYTES);

    int tid = threadIdx.x, lane = tid & 31, wid = tid >> 5;
    int rowBase = blockIdx.y * 128;    // [0, 4096)
    int colBase = blockIdx.x * 128;    // [0, 12288)
    if (tid < 128) clab[tid] = labels[(colBase & (BSZ - 1)) + tid];

    int warpM = wid & 3;               // 4 warps along M (32 rows each)
    int warpN = wid >> 2;              // 2 warps along N (64 cols each)

    // ldmatrix lane offsets (bytes, within one operand); += 32 B per k-step
    uint32_t offA[2], offB[4];
    #pragma unroll
    for (int mt = 0; mt < 2; mt++) {
        int r  = warpM * 32 + mt * 16 + (lane & 15);
        int kc = (lane >> 4) * 8;
        offA[mt] = (uint32_t)(r * ASTRIDE + kc) * 2u;
    }
    #pragma unroll
    for (int np = 0; np < 4; np++) {
        int n  = warpN * 64 + np * 16 + (lane & 7) + ((lane & 16) >> 1);
        int kc = ((lane >> 3) & 1) * 8;
        offB[np] = (uint32_t)(n * ASTRIDE + kc) * 2u;
    }

    float acc[2][8][4];
    #pragma unroll
    for (int mt = 0; mt < 2; mt++)
        #pragma unroll
        for (int nt = 0; nt < 8; nt++)
            #pragma unroll
            for (int c = 0; c < 4; c++) acc[mt][nt][c] = 0.0f;

    int ldrow = tid >> 2, ldg = (tid & 3) * 8;     // 64 rows/pass, 16 B per row
    const __nv_bfloat16* gA = g_Fh + (size_t)(rowBase + ldrow) * DIM + ldg;
    const __nv_bfloat16* gB = g_Fh + (size_t)(colBase + ldrow) * DIM + ldg;
    uint32_t srow = (uint32_t)(ldrow * ASTRIDE + ldg) * 2u;

    auto issue = [&](int stg, int kt) {
        uint32_t so = sbase + (uint32_t)stg * STAGEBYTES;
        #pragma unroll
        for (int p = 0; p < 2; p++) {
            uint32_t ro = (uint32_t)(p * 64 * ASTRIDE * 2) + srow;
            cp_async16(so + ro,           gA + (size_t)p * 64 * DIM + kt);
            cp_async16(so + OPBYTES + ro, gB + (size_t)p * 64 * DIM + kt);
        }
    };

    issue(0, 0);  CP_COMMIT();
    issue(1, 32); CP_COMMIT();

    #pragma unroll
    for (int i = 0; i < 8; i++) {
        if (i < 7) { CP_WAIT(1); } else { CP_WAIT(0); }
        __syncthreads();                       // stage i ready; stage (i+2)%3 free
        if (i < 6) { issue((i + 2) % NSTAGE, (i + 2) * 32); CP_COMMIT(); }

        uint32_t sa = sbase + (uint32_t)(i % NSTAGE) * STAGEBYTES;
        uint32_t sb = sa + OPBYTES;
        #pragma unroll
        for (int ks = 0; ks < 2; ks++) {
            uint32_t a[2][4], b[4][4];
            #pragma unroll
            for (int mt = 0; mt < 2; mt++)
                asm volatile("ldmatrix.sync.aligned.m8n8.x4.shared.b16 "
                             "{%0,%1,%2,%3}, [%4];"
                             : "=r"(a[mt][0]), "=r"(a[mt][1]),
                               "=r"(a[mt][2]), "=r"(a[mt][3])
                             : "r"(sa + offA[mt] + ks * 32u));
            #pragma unroll
            for (int np = 0; np < 4; np++)
                asm volatile("ldmatrix.sync.aligned.m8n8.x4.shared.b16 "
                             "{%0,%1,%2,%3}, [%4];"
                             : "=r"(b[np][0]), "=r"(b[np][1]),
                               "=r"(b[np][2]), "=r"(b[np][3])
                             : "r"(sb + offB[np] + ks * 32u));
            #pragma unroll
            for (int mt = 0; mt < 2; mt++)
                #pragma unroll
                for (int nt = 0; nt < 8; nt++) {
                    uint32_t b0 = b[nt >> 1][(nt & 1) * 2];
                    uint32_t b1 = b[nt >> 1][(nt & 1) * 2 + 1];
                    asm volatile(
                        "mma.sync.aligned.m16n8k16.row.col.f32.bf16.bf16.f32 "
                        "{%0,%1,%2,%3}, {%4,%5,%6,%7}, {%8,%9}, {%0,%1,%2,%3};"
                        : "+f"(acc[mt][nt][0]), "+f"(acc[mt][nt][1]),
                          "+f"(acc[mt][nt][2]), "+f"(acc[mt][nt][3])
                        : "r"(a[mt][0]), "r"(a[mt][1]), "r"(a[mt][2]), "r"(a[mt][3]),
                          "r"(b0), "r"(b1));
                }
        }
    }

    // Epilogue: masked max per row, straight from C fragments.
    int gid = lane >> 2, qid = lane & 3;
    int mat = colBase >> 12;
    #pragma unroll
    for (int mt = 0; mt < 2; mt++)
        #pragma unroll
        for (int half = 0; half < 2; half++) {
            int grow = rowBase + warpM * 32 + mt * 16 + half * 8 + gid;
            int rl   = labels[grow];
            float mx = -2.0f;
            #pragma unroll
            for (int nt = 0; nt < 8; nt++) {
                int c0 = warpN * 64 + nt * 8 + qid * 2;
                if (clab[c0]     != rl) mx = fmaxf(mx, acc[mt][nt][half * 2]);
                if (clab[c0 + 1] != rl) mx = fmaxf(mx, acc[mt][nt][half * 2 + 1]);
            }
            mx = fmaxf(mx, __shfl_xor_sync(0xffffffffu, mx, 1));
            mx = fmaxf(mx, __shfl_xor_sync(0xffffffffu, mx, 2));
            if (qid == 0)
                atomicMax(&g_maxkey[mat * BSZ + grow], enc_key(mx));
        }
}

// ============================================================================
// Kernel 3: deterministic finalize -> scalar mean loss
// ============================================================================
__global__ __launch_bounds__(1024) void finalize_kernel(float* __restrict__ out) {
    __shared__ float sm[32];
    float sum = 0.0f;
    for (int i = threadIdx.x; i < BSZ; i += 1024) {
        float daa = dec_key(g_maxkey[i]);
        #pragma unroll
        for (int v = 0; v < 2; v++) {
            float dap  = dec_key(g_maxkey[(1 + v) * BSZ + i]);
            float best = fmaxf(daa, dap);
            float neg  = sqrtf(fmaxf(2.0f - 2.0f * best, EPSQ));
            float pos  = sqrtf(fmaxf(2.0f - 2.0f * g_pos[v * BSZ + i], EPSQ));
            sum += fmaxf(pos - neg + MARGIN, 0.0f);
        }
    }
    #pragma unroll
    for (int o = 16; o; o >>= 1) sum += __shfl_down_sync(0xffffffffu, sum, o);
    int w = threadIdx.x >> 5, l = threadIdx.x & 31;
    if (l == 0) sm[w] = sum;
    __syncthreads();
    if (w == 0) {
        float t = sm[l];
        #pragma unroll
        for (int o = 16; o; o >>= 1) t += __shfl_down_sync(0xffffffffu, t, o);
        if (l == 0) out[0] = t / (2.0f * BSZ);
    }
}

// ============================================================================
extern "C" void kernel_launch(void* const* d_in, const int* in_sizes, int n_in,
                              void* d_out, int out_size) {
    const float* anchor   = (const float*)d_in[0];
    const float* positive = (const float*)d_in[1];
    const int*   labels   = (const int*)d_in[2];
    float*       out      = (float*)d_out;

    cudaFuncSetAttribute(gemm_max_mma,
                         cudaFuncAttributeMaxDynamicSharedMemorySize, SMEM_DYN);

    normalize_kernel<<<BSZ / 8, 256>>>(anchor, positive);
    gemm_max_mma<<<dim3(NF / 128, BSZ / 128), 256, SMEM_DYN>>>(labels);
    finalize_kernel<<<1, 1024>>>(out);
}